// round 14
// baseline (speedup 1.0000x reference)
#include <cuda_runtime.h>

#define HH 1024
#define WW 1024
#define MM 512            // 16 segments * 32 samples
#define TW 16.0f          // window half-width used only for list assignment
#define BCAP 128          // max edges per warp-band list
#define NT 256

__global__ __launch_bounds__(NT)
void bvr_fused_kernel(const float* __restrict__ cp,
                      const float* __restrict__ color,
                      float* __restrict__ out)
{
    __shared__ float2 s_pts[MM + 2];    // sampled path points (+wrap pad)
    __shared__ float2 s_lst[8][BCAP];   // per-warp-band lists: {w/2, xc/2}
    __shared__ int    s_lcnt[8];
    __shared__ float  s_btot[9];        // per 128-px bucket weight totals

    const int tid = threadIdx.x;
    const int y   = blockIdx.x;
    const float fy = (float)y;

    if (tid < 9) { s_btot[tid] = 0.0f; if (tid < 8) s_lcnt[tid] = 0; }

    // ---- 1. Sample Bezier path (2 points per thread) ----
    #pragma unroll
    for (int it = 0; it < 2; ++it) {
        int i = tid + it * NT;
        int s = i >> 5;
        int j = i & 31;
        float t  = (float)j * (1.0f / 31.0f);   // j=31 -> exactly 1.0f
        float mt = 1.0f - t;
        float b0 = mt * mt * mt;
        float b1 = 3.0f * mt * mt * t;
        float b2 = 3.0f * mt * t * t;
        float b3 = t * t * t;
        const float* p = cp + 6 * s;
        float px = b0 * p[0] + b1 * p[2] + b2 * p[4] + b3 * p[6];
        float py = b0 * p[1] + b1 * p[3] + b2 * p[5] + b3 * p[7];
        float2 pt = make_float2(px, py);
        s_pts[i] = pt;
        if (i == 0) s_pts[MM] = pt;             // wrap point for edge 511
    }
    __syncthreads();

    // ---- 2. Compact edge pair (2t, 2t+1); dual-push into warp-band lists ----
    {
        const int e0 = tid * 2;
        float4 pp = *(const float4*)&s_pts[e0];     // points e0, e0+1 (LDS.128)
        float2 p2 = s_pts[e0 + 2];                  // point e0+2 (LDS.64)
        float2 eP0[2] = { make_float2(pp.x, pp.y), make_float2(pp.z, pp.w) };
        float2 eP1[2] = { make_float2(pp.z, pp.w), p2 };

        #pragma unroll
        for (int h = 0; h < 2; ++h) {
            float2 p0 = eP0[h];
            float2 p1 = eP1[h];
            float dy = p1.y - p0.y;
            if (fabsf(dy) < 1e-6f) continue;        // coeff == 0 in reference

            float ba = p0.y - 1.2f * dy;            // |w|>1e-10 needs t in [-1.2,2.2]
            float bb = p0.y + 2.2f * dy;
            if (fy < fminf(ba, bb) || fy > fmaxf(ba, bb)) continue;

            float t = __fdividef(fy - p0.y, dy + 1e-8f);
            // v1*v2 = 1 / (1 + e^-20t + e^(20t-20) + e^-20)  (exact expansion)
            float ea = __expf(-20.0f * t);
            float eb = __expf(20.0f * (t - 1.0f));
            float denom = 1.0f + ea + eb + 2.0611537e-9f;
            if (denom > 1e10f) continue;            // |w| < 1e-10

            float coeff = (dy > 0.0f) ? 1.0f : -1.0f;
            float w  = __fdividef(coeff, denom);
            float xc = p0.x + t * (p1.x - p0.x);
            if (xc < -TW) continue;                 // sigma ~0 across whole row

            int xlo = (int)ceilf(xc - TW);
            xlo = max(0, min(xlo, WW));
            int b = xlo >> 7;                       // 0..7 bands, 8 = right of row

            atomicAdd(&s_btot[b], w);
            float2 entry = make_float2(0.5f * w, 0.5f * xc);
            if (b < 8) {
                int slot = atomicAdd(&s_lcnt[b], 1);
                if (slot < BCAP) s_lst[b][slot] = entry;
                // window [xlo, xlo+33) can spill into the next 128-px band
                if (b < 7 && (xlo & 127) > 95) {
                    int s2 = atomicAdd(&s_lcnt[b + 1], 1);
                    if (s2 < BCAP) s_lst[b + 1][s2] = entry;
                }
            }
        }
    }
    __syncthreads();

    // ---- 3. Direct evaluation: suffix buckets (full w) + own-band list ----
    const int wrp = tid >> 5;                       // warp covers px [wrp*128,+128)
    const float hbf = 0.5f * (float)(tid * 4);      // half of first pixel coord

    float wbase = 0.0f;
    #pragma unroll
    for (int j = 1; j <= 8; ++j)
        wbase += (j > wrp) ? s_btot[j] : 0.0f;      // predicated

    float wa0 = wbase, wa1 = wbase, wa2 = wbase, wa3 = wbase;

    const int cnt = min(s_lcnt[wrp], BCAP);         // warp-uniform
    #pragma unroll 2
    for (int s = 0; s < cnt; ++s) {
        float2 ek = s_lst[wrp][s];                  // broadcast LDS.64 {w/2, xc/2}
        float hw = ek.x;
        float hu = ek.y - hbf;                      // (xc - x0)/2
        // w * sigmoid(xc - x) = hw * tanh((xc-x)/2) + hw   (saturates, exact)
        float t0, t1, t2, t3;
        asm("tanh.approx.f32 %0, %1;" : "=f"(t0) : "f"(hu));
        asm("tanh.approx.f32 %0, %1;" : "=f"(t1) : "f"(hu - 0.5f));
        asm("tanh.approx.f32 %0, %1;" : "=f"(t2) : "f"(hu - 1.0f));
        asm("tanh.approx.f32 %0, %1;" : "=f"(t3) : "f"(hu - 1.5f));
        wa0 += fmaf(hw, t0, hw);
        wa1 += fmaf(hw, t1, hw);
        wa2 += fmaf(hw, t2, hw);
        wa3 += fmaf(hw, t3, hw);
    }

    // ---- 4. Alpha via tanh.approx + output ----
    const float cr = __ldg(color + 0);
    const float cg = __ldg(color + 1);
    const float cb = __ldg(color + 2);

    float wind[4] = {wa0, wa1, wa2, wa3};
    float4* orow = (float4*)out + (size_t)y * WW + tid * 4;
    #pragma unroll
    for (int q = 0; q < 4; ++q) {
        float th;                                   // sigmoid(4w)=0.5+0.5tanh(2w)
        asm("tanh.approx.f32 %0, %1;" : "=f"(th) : "f"(2.0f * wind[q]));
        float a = fmaf(0.5f, th, 0.5f);
        orow[q] = make_float4(cr, cg, cb, a);
    }
}

extern "C" void kernel_launch(void* const* d_in, const int* in_sizes, int n_in,
                              void* d_out, int out_size)
{
    const float* cp    = (const float*)d_in[0];   // (49, 2) float32
    const float* color = (const float*)d_in[1];   // (3,)   float32
    float* out = (float*)d_out;                   // (1024, 1024, 4) float32
    (void)in_sizes; (void)n_in; (void)out_size;
    bvr_fused_kernel<<<HH, NT>>>(cp, color, out);
}

// round 16
// speedup vs baseline: 1.1400x; 1.1400x over previous
#include <cuda_runtime.h>

#define HH 1024
#define WW 1024
#define MM 512            // 16 segments * 32 samples
#define TW 16.0f          // window half-width used only for bucketing
#define BCAP 96           // max edges per 128-px bucket
#define NT 256

// Per-edge tables (prep -> render)
__device__ float4 g_e1[MM];   // ymin, ymax, y0, rinv
__device__ float4 g_e2[MM];   // x0, dx, coeff, pad

// ---------------- Phase A: sample path, build edge tables ----------------
__global__ void bvr_prep_kernel(const float* __restrict__ cp)
{
    __shared__ float2 s_pts[MM];
    const int i = threadIdx.x;          // 512 threads

    {
        int s = i >> 5;
        int j = i & 31;
        float t  = (float)j * (1.0f / 31.0f);
        float mt = 1.0f - t;
        float b0 = mt * mt * mt;
        float b1 = 3.0f * mt * mt * t;
        float b2 = 3.0f * mt * t * t;
        float b3 = t * t * t;
        const float* p = cp + 6 * s;
        float px = b0 * p[0] + b1 * p[2] + b2 * p[4] + b3 * p[6];
        float py = b0 * p[1] + b1 * p[3] + b2 * p[5] + b3 * p[7];
        s_pts[i] = make_float2(px, py);
    }
    __syncthreads();

    float2 p0 = s_pts[i];
    float2 p1 = s_pts[(i + 1) & (MM - 1)];
    float dy = p1.y - p0.y;

    if (fabsf(dy) < 1e-6f) {
        g_e1[i] = make_float4(1e30f, -1e30f, 0.f, 0.f);   // impossible y-range
        g_e2[i] = make_float4(0.f, 0.f, 0.f, 0.f);
        return;
    }
    float coeff = (dy > 0.0f) ? 1.0f : -1.0f;
    float rinv  = __fdividef(1.0f, dy + 1e-8f);
    // |w| > ~1e-10 requires t in ~[-1.2, 2.2]
    float ya = p0.y - 1.2f * dy;
    float yb = p0.y + 2.2f * dy;
    g_e1[i] = make_float4(fminf(ya, yb), fmaxf(ya, yb), p0.y, rinv);
    g_e2[i] = make_float4(p0.x, p1.x - p0.x, coeff, 0.f);
}

// ---------------- Phase B: one block per row ----------------
__global__ __launch_bounds__(NT)
void bvr_render_kernel(const float* __restrict__ color,
                       float* __restrict__ out)
{
    __shared__ float2 s_bk[9][BCAP];    // bucket lists: {w/2, xc/2}
    __shared__ int    s_bcnt[9];
    __shared__ float  s_btot[9];

    const int tid = threadIdx.x;
    const int y   = blockIdx.x;
    const float fy = (float)y;

    if (tid < 9) { s_bcnt[tid] = 0; s_btot[tid] = 0.0f; }
    __syncthreads();

    // ---- 1. Compact active edges into 128-px buckets (2 edges/thread) ----
    #pragma unroll
    for (int it = 0; it < 2; ++it) {
        int e = tid + it * NT;
        float4 e1 = g_e1[e];                        // ymin, ymax, y0, rinv
        if (fy < e1.x || fy > e1.y) continue;       // most edges exit here

        float4 e2 = g_e2[e];                        // x0, dx, coeff
        float t  = (fy - e1.z) * e1.w;
        // v1*v2 = 1 / (1 + e^-20t + e^(20t-20) + e^-20)  (exact expansion)
        float ea = __expf(-20.0f * t);
        float eb = __expf(20.0f * (t - 1.0f));
        float denom = 1.0f + ea + eb + 2.0611537e-9f;
        if (denom > 1e10f) continue;                // |w| < 1e-10

        float w  = __fdividef(e2.z, denom);
        float xc = e2.x + t * e2.y;
        if (xc < -TW) continue;                     // sigma ~0 across whole row

        int xlo = (int)ceilf(xc - TW);
        xlo = max(0, min(xlo, WW));
        int bkt = min(xlo >> 7, 8);                 // 0..7 bands, 8 = right of row

        int slot = atomicAdd(&s_bcnt[bkt], 1);
        s_bk[bkt][slot] = make_float2(0.5f * w, 0.5f * xc);
        atomicAdd(&s_btot[bkt], w);
    }
    __syncthreads();

    // ---- 2. Direct evaluation: suffix buckets (full w) + nearby buckets ----
    const int wrp = tid >> 5;                       // warp covers px [wrp*128,+128)
    const float hbf = 0.5f * (float)(tid * 4);      // half of first pixel coord

    float wbase = 0.0f;
    #pragma unroll
    for (int j = 1; j <= 8; ++j)
        wbase += (j > wrp) ? s_btot[j] : 0.0f;      // predicated

    float wa0 = wbase, wa1 = wbase, wa2 = wbase, wa3 = wbase;

    // Edges whose transition can touch this warp's band live in buckets
    // wrp-1 and wrp. sigmoid saturates naturally -> exact, no window clamp.
    const int bb0 = (wrp > 0) ? (wrp - 1) : 0;
    for (int bb = bb0; bb <= wrp; ++bb) {
        const int cnt = s_bcnt[bb];                 // warp-uniform
        for (int s = 0; s < cnt; ++s) {
            float2 ek = s_bk[bb][s];                // broadcast LDS.64 {w/2, xc/2}
            float hw = ek.x;
            float hu = ek.y - hbf;                  // (xc - x0)/2
            // w * sigmoid(xc - x) = hw * tanh((xc-x)/2) + hw
            float t0, t1, t2, t3;
            asm("tanh.approx.f32 %0, %1;" : "=f"(t0) : "f"(hu));
            asm("tanh.approx.f32 %0, %1;" : "=f"(t1) : "f"(hu - 0.5f));
            asm("tanh.approx.f32 %0, %1;" : "=f"(t2) : "f"(hu - 1.0f));
            asm("tanh.approx.f32 %0, %1;" : "=f"(t3) : "f"(hu - 1.5f));
            wa0 += fmaf(hw, t0, hw);
            wa1 += fmaf(hw, t1, hw);
            wa2 += fmaf(hw, t2, hw);
            wa3 += fmaf(hw, t3, hw);
        }
    }

    // ---- 3. Alpha via tanh.approx + output ----
    const float cr = __ldg(color + 0);
    const float cg = __ldg(color + 1);
    const float cb = __ldg(color + 2);

    float wind[4] = {wa0, wa1, wa2, wa3};
    float4* orow = (float4*)out + (size_t)y * WW + tid * 4;
    #pragma unroll
    for (int q = 0; q < 4; ++q) {
        float th;                                   // sigmoid(4w)=0.5+0.5tanh(2w)
        asm("tanh.approx.f32 %0, %1;" : "=f"(th) : "f"(2.0f * wind[q]));
        float a = fmaf(0.5f, th, 0.5f);
        orow[q] = make_float4(cr, cg, cb, a);
    }
}

extern "C" void kernel_launch(void* const* d_in, const int* in_sizes, int n_in,
                              void* d_out, int out_size)
{
    const float* cp    = (const float*)d_in[0];   // (49, 2) float32
    const float* color = (const float*)d_in[1];   // (3,)   float32
    float* out = (float*)d_out;                   // (1024, 1024, 4) float32
    (void)in_sizes; (void)n_in; (void)out_size;
    bvr_prep_kernel<<<1, MM>>>(cp);
    bvr_render_kernel<<<HH, NT>>>(color, out);
}